// round 17
// baseline (speedup 1.0000x reference)
#include <cuda_runtime.h>
#include <cstdint>

// VoxelHashTable: 2-level hash-grid trilinear interpolation.
// Inputs (metadata order):
//   d_in[0] query_pts (M,3) f32
//   d_in[1] feats0    (n0,32) f32
//   d_in[2] feats1    (n1,32) f32
//   d_in[3] h2v0      (2^20) i32
//   d_in[4] h2v1      (2^20) i32
// Output: (M, 64) f32  — [level0 32 | level1 32]
//
// Warp layout (1 warp = 4 queries = two pairs A, B). Per-pair lane roles:
//   half = lane>>4, level = (lane>>3)&1, s = lane&7 (float4 chunk)
//
// Structure = R15 broadcast probes x R7 two-pair batching:
//   - Hash probes are BROADCAST loads h[base + COFF(t)] (compile-time corner
//     offsets): 4 distinct addresses per probe instruction, ~1.0cyc/wf
//     cross-instruction rate, zero shuffles. (Validated -3.4us in R15.)
//   - Prologue issues ALL 16 probes (both pairs) back-to-back, so gather A
//     overlaps any straggling B probes and gather B starts fully resolved.
//     (Two-pair batching validated -2.6us in R7.)
// Reciprocal-multiply instead of divide (validated: rel_err 6.6e-8).
// __launch_bounds__(256, 6): 40-reg budget for the 16 live probe results
// ((256,7) truncates to 32 regs and spills; (256,8) cannot hold 16 probes).

#define TSIZE_MASK ((1 << 20) - 1)

// PRIMES % 2^20 (exact):
#define PMX 455773
#define PMY 475301
#define PMZ 655287

#define INV_RES0 (1.0f / 0.12f)
#define INV_RES1 (1.0f / 0.24f)   // 0.24f == float32(0.12*2.0)

// Compile-time corner offset into the hash sum: corner bits (x,y,z)=(4,2,1).
#define COFF(c) (((c) & 4 ? PMX : 0) + ((c) & 2 ? PMY : 0) + ((c) & 1 ? PMZ : 0))

__global__ __launch_bounds__(256, 6) void voxel_hash_kernel(
    const float* __restrict__ q,
    const float* __restrict__ f0,
    const float* __restrict__ f1,
    const int* __restrict__ h0,
    const int* __restrict__ h1,
    float* __restrict__ out,
    int M)
{
    const int wid  = (blockIdx.x * blockDim.x + threadIdx.x) >> 5;
    const int lane = threadIdx.x & 31;

    const int level = (lane >> 3) & 1;
    const int s     = lane & 7;
    const int half  = lane >> 4;

    const int base = wid * 4;
    int qA = base + half;
    int qB = base + 2 + half;
    const bool actA = qA < M;
    const bool actB = qB < M;
    if (qA >= M) qA = M - 1;
    if (qB >= M) qB = M - 1;

    const float inv_res = level ? INV_RES1 : INV_RES0;
    const int*   __restrict__ hp = level ? h1 : h0;
    const float* __restrict__ fp = (level ? f1 : f0) + s * 4;

    // ---- Prologue: both pairs' query points ----
    const float qAx = __ldg(q + qA * 3 + 0);
    const float qAy = __ldg(q + qA * 3 + 1);
    const float qAz = __ldg(q + qA * 3 + 2);
    const float qBx = __ldg(q + qB * 3 + 0);
    const float qBy = __ldg(q + qB * 3 + 1);
    const float qBz = __ldg(q + qB * 3 + 2);

    const float sxA = qAx * inv_res, syA = qAy * inv_res, szA = qAz * inv_res;
    const float bxA = floorf(sxA), byA = floorf(syA), bzA = floorf(szA);
    const float fxA = sxA - bxA, fyA = syA - byA, fzA = szA - bzA;
    const int hbaseA = (int)bxA * PMX + (int)byA * PMY + (int)bzA * PMZ;

    const float sxB = qBx * inv_res, syB = qBy * inv_res, szB = qBz * inv_res;
    const float bxB = floorf(sxB), byB = floorf(syB), bzB = floorf(szB);
    const float fxB = sxB - bxB, fyB = syB - byB, fzB = szB - bzB;
    const int hbaseB = (int)bxB * PMX + (int)byB * PMY + (int)bzB * PMZ;

    // ---- All 16 broadcast probes issued back-to-back ----
    int vA[8], vB[8];
    #pragma unroll
    for (int t = 0; t < 8; ++t) {
        const unsigned hvA = ((unsigned)(hbaseA + COFF(t))) & TSIZE_MASK;
        vA[t] = __ldg(hp + hvA);
    }
    #pragma unroll
    for (int t = 0; t < 8; ++t) {
        const unsigned hvB = ((unsigned)(hbaseB + COFF(t))) & TSIZE_MASK;
        vB[t] = __ldg(hp + hvB);
    }

    // ---- Gather A ----
    {
        const float gx = 1.0f - fxA, gy = 1.0f - fyA, gz = 1.0f - fzA;
        float4 acc = make_float4(0.f, 0.f, 0.f, 0.f);
        #pragma unroll
        for (int t = 0; t < 8; ++t) {
            // ((wx*wy)*wz) multiply order matches reference prod(axis=2).
            const float w = ((t & 4) ? fxA : gx) *
                            ((t & 2) ? fyA : gy) *
                            ((t & 1) ? fzA : gz);
            const int v = vA[t];
            if (v >= 0) {
                const float4 f = __ldg((const float4*)(fp + (size_t)v * 32));
                acc.x = fmaf(f.x, w, acc.x);
                acc.y = fmaf(f.y, w, acc.y);
                acc.z = fmaf(f.z, w, acc.z);
                acc.w = fmaf(f.w, w, acc.w);
            }
        }
        if (actA) {
            *(float4*)(out + (size_t)qA * 64 + level * 32 + s * 4) = acc;
        }
    }

    // ---- Gather B ----
    {
        const float gx = 1.0f - fxB, gy = 1.0f - fyB, gz = 1.0f - fzB;
        float4 acc = make_float4(0.f, 0.f, 0.f, 0.f);
        #pragma unroll
        for (int t = 0; t < 8; ++t) {
            const float w = ((t & 4) ? fxB : gx) *
                            ((t & 2) ? fyB : gy) *
                            ((t & 1) ? fzB : gz);
            const int v = vB[t];
            if (v >= 0) {
                const float4 f = __ldg((const float4*)(fp + (size_t)v * 32));
                acc.x = fmaf(f.x, w, acc.x);
                acc.y = fmaf(f.y, w, acc.y);
                acc.z = fmaf(f.z, w, acc.z);
                acc.w = fmaf(f.w, w, acc.w);
            }
        }
        if (actB) {
            *(float4*)(out + (size_t)qB * 64 + level * 32 + s * 4) = acc;
        }
    }
}

extern "C" void kernel_launch(void* const* d_in, const int* in_sizes, int n_in,
                              void* d_out, int out_size)
{
    const float* q  = (const float*)d_in[0];
    const float* f0 = (const float*)d_in[1];
    const float* f1 = (const float*)d_in[2];
    const int*   h0 = (const int*)d_in[3];
    const int*   h1 = (const int*)d_in[4];
    float* out = (float*)d_out;

    const int M = in_sizes[0] / 3;
    const int warps = (M + 3) / 4;          // 4 queries per warp

    const int warps_per_block = 8;
    const int blocks = (warps + warps_per_block - 1) / warps_per_block;
    voxel_hash_kernel<<<blocks, warps_per_block * 32>>>(q, f0, f1, h0, h1, out, M);
}